// round 2
// baseline (speedup 1.0000x reference)
#include <cuda_runtime.h>

#define B_   64
#define S_   2048
#define H_   1024
#define SPLIT 32
#define CHUNK (S_ / SPLIT)      // 64 timesteps per CTA
#define WARPS 8
#define THREADS 256

// Scratch (allocation-free: __device__ globals)
__device__ float g_expE [B_ * S_];             // exp(tanh(score)) per (b,s)
__device__ float g_partL[B_ * SPLIT];          // partial sum of exp per chunk
__device__ float g_partC[B_ * SPLIT * H_];     // partial context per chunk (8 MiB)
__device__ float g_linv [B_];                  // 1 / sum_exp per batch

// ---------------------------------------------------------------------------
// Pass 1: single DRAM read of rnn_output. Warp = one timestep at a time.
// Phase A: dot(x_s, w) from global (fills L1), shuffle reduce, t=exp(tanh(.)).
// Phase B: re-read x_s (L1/L2 hit; pointer laundered so ptxas can't keep the
//          32 float4 registers alive across the reduce) and accumulate t*x.
// tanh output is in [-1,1] so softmax needs no max subtraction.
// ---------------------------------------------------------------------------
__global__ __launch_bounds__(THREADS)
void pass1_kernel(const float* __restrict__ x,
                  const float* __restrict__ w,
                  const float* __restrict__ bptr)
{
    __shared__ float ws[H_];                 // 4 KB weight cache
    __shared__ float red[WARPS * H_];        // 32 KB cross-warp reduction
    __shared__ float lred[WARPS];

    const int b     = blockIdx.x / SPLIT;
    const int chunk = blockIdx.x % SPLIT;
    const int tid   = threadIdx.x;
    const int warp  = tid >> 5;
    const int lane  = tid & 31;
    const float bias = __ldg(bptr);

    for (int i = tid; i < H_ / 4; i += THREADS)
        reinterpret_cast<float4*>(ws)[i] =
            reinterpret_cast<const float4*>(w)[i];
    __syncthreads();

    float caccx[8], caccy[8], caccz[8], caccw[8];
    #pragma unroll
    for (int i = 0; i < 8; i++) {
        caccx[i] = 0.f; caccy[i] = 0.f; caccz[i] = 0.f; caccw[i] = 0.f;
    }
    float lsum = 0.f;

    const int s0 = chunk * CHUNK;

    #pragma unroll 1
    for (int it = 0; it < CHUNK / WARPS; it++) {
        const int s = s0 + it * WARPS + warp;
        const float4* xp = reinterpret_cast<const float4*>(
            x + ((size_t)b * S_ + s) * H_);

        // Phase A: dot product (x streams through L1)
        float dot = 0.f;
        #pragma unroll
        for (int i = 0; i < 8; i++) {
            float4 xv = xp[i * 32 + lane];
            float4 wv = reinterpret_cast<float4*>(ws)[i * 32 + lane];
            dot += xv.x * wv.x + xv.y * wv.y + xv.z * wv.z + xv.w * wv.w;
        }
        #pragma unroll
        for (int off = 16; off; off >>= 1)
            dot += __shfl_xor_sync(0xffffffffu, dot, off);

        const float t = __expf(tanhf(dot + bias));
        if (lane == 0) g_expE[(size_t)b * S_ + s] = t;
        lsum += t;

        // Phase B: re-read x via laundered pointer (L1 hit), accumulate t*x
        const float4* xq;
        asm("mov.b64 %0, %1;" : "=l"(xq) : "l"(xp));
        #pragma unroll
        for (int i = 0; i < 8; i++) {
            float4 xv = xq[i * 32 + lane];
            caccx[i] += t * xv.x;
            caccy[i] += t * xv.y;
            caccz[i] += t * xv.z;
            caccw[i] += t * xv.w;
        }
    }

    // per-warp partials -> smem
    #pragma unroll
    for (int i = 0; i < 8; i++) {
        float4 v = make_float4(caccx[i], caccy[i], caccz[i], caccw[i]);
        reinterpret_cast<float4*>(red + warp * H_)[i * 32 + lane] = v;
    }
    if (lane == 0) lred[warp] = lsum;
    __syncthreads();

    // combine 8 warps; each thread owns one float4 of H
    for (int h4 = tid; h4 < H_ / 4; h4 += THREADS) {
        float4 acc = reinterpret_cast<float4*>(red)[h4];
        #pragma unroll
        for (int wI = 1; wI < WARPS; wI++) {
            float4 v = reinterpret_cast<float4*>(red + wI * H_)[h4];
            acc.x += v.x; acc.y += v.y; acc.z += v.z; acc.w += v.w;
        }
        reinterpret_cast<float4*>(
            g_partC + ((size_t)b * SPLIT + chunk) * H_)[h4] = acc;
    }
    if (tid == 0) {
        float l = 0.f;
        #pragma unroll
        for (int i = 0; i < WARPS; i++) l += lred[i];
        g_partL[b * SPLIT + chunk] = l;
    }
}

// ---------------------------------------------------------------------------
// Pass 2: per-batch combine of SPLIT partials -> context [B,H] and 1/l.
// ---------------------------------------------------------------------------
__global__ __launch_bounds__(THREADS)
void pass2_kernel(float* __restrict__ ctx_out)
{
    const int b   = blockIdx.x;
    const int tid = threadIdx.x;
    __shared__ float s_inv;

    if (tid < 32) {
        float l = 0.f;
        #pragma unroll
        for (int c = tid; c < SPLIT; c += 32)
            l += g_partL[b * SPLIT + c];
        #pragma unroll
        for (int off = 16; off; off >>= 1)
            l += __shfl_xor_sync(0xffffffffu, l, off);
        if (tid == 0) {
            float inv = 1.f / l;
            s_inv = inv;
            g_linv[b] = inv;
        }
    }
    __syncthreads();
    const float inv = s_inv;

    for (int h4 = tid; h4 < H_ / 4; h4 += THREADS) {
        float4 acc = make_float4(0.f, 0.f, 0.f, 0.f);
        #pragma unroll
        for (int c = 0; c < SPLIT; c++) {
            float4 v = reinterpret_cast<const float4*>(
                g_partC + ((size_t)b * SPLIT + c) * H_)[h4];
            acc.x += v.x; acc.y += v.y; acc.z += v.z; acc.w += v.w;
        }
        acc.x *= inv; acc.y *= inv; acc.z *= inv; acc.w *= inv;
        reinterpret_cast<float4*>(ctx_out + (size_t)b * H_)[h4] = acc;
    }
}

// ---------------------------------------------------------------------------
// Pass 3: weights[b,s] = expE[b,s] / l[b]   (float4: S_ % 4 == 0)
// ---------------------------------------------------------------------------
__global__ __launch_bounds__(THREADS)
void pass3_kernel(float* __restrict__ w_out)
{
    const int i = blockIdx.x * THREADS + threadIdx.x;  // over B_*S_/4
    if (i < B_ * S_ / 4) {
        const int b = i / (S_ / 4);
        const float inv = g_linv[b];
        float4 e = reinterpret_cast<const float4*>(g_expE)[i];
        e.x *= inv; e.y *= inv; e.z *= inv; e.w *= inv;
        reinterpret_cast<float4*>(w_out)[i] = e;
    }
}

extern "C" void kernel_launch(void* const* d_in, const int* in_sizes, int n_in,
                              void* d_out, int out_size)
{
    const float* x    = (const float*)d_in[0];   // rnn_output [B,S,H]
    const float* w    = (const float*)d_in[1];   // attn_w [H]
    const float* bptr = (const float*)d_in[2];   // attn_b scalar

    float* out = (float*)d_out;                  // context [B,H] then weights [B,S]
    float* ctx_out = out;
    float* wts_out = out + (size_t)B_ * H_;

    pass1_kernel<<<B_ * SPLIT, THREADS>>>(x, w, bptr);
    pass2_kernel<<<B_, THREADS>>>(ctx_out);
    pass3_kernel<<<(B_ * S_ / 4 + THREADS - 1) / THREADS, THREADS>>>(wts_out);
}

// round 3
// speedup vs baseline: 1.3363x; 1.3363x over previous
#include <cuda_runtime.h>

#define B_    64
#define S_    2048
#define H_    1024
#define SPLIT 16
#define CHUNK (S_ / SPLIT)      // 128 timesteps per CTA
#define TILE  8
#define THREADS 256             // one float4 column slice per thread

// Scratch (allocation-free: __device__ globals)
__device__ float g_expE [B_ * S_];             // exp(tanh(score)) per (b,s)
__device__ float g_partL[B_ * SPLIT];          // partial sum of exp per chunk
__device__ float g_partC[B_ * SPLIT * H_];     // partial context per chunk (4 MiB)
__device__ float g_linv [B_];                  // 1 / sum_exp per batch

// ---------------------------------------------------------------------------
// Pass 1: single DRAM read of rnn_output.
// Thread t owns H columns [4t, 4t+4). Per tile of 8 timesteps:
//   Phase A: load xr[s] (float4, fully coalesced: CTA covers the whole row),
//            partial dot xr[s]·w4, block-reduce 8 dots, 8 threads do
//            t=exp(tanh(.)) (tanh in [-1,1] -> no softmax max needed).
//   Phase B: acc4 += t[s] * xr[s]   (data consumed from registers, read once)
// ---------------------------------------------------------------------------
__global__ __launch_bounds__(THREADS)
void pass1_kernel(const float* __restrict__ x,
                  const float* __restrict__ w,
                  const float* __restrict__ bptr)
{
    __shared__ float red[(THREADS / 32) * TILE];   // [warp][s] partial dots
    __shared__ float tt[TILE];                     // broadcast t per timestep
    __shared__ float lred[TILE];                   // per-owner lsum at end

    const int b     = blockIdx.x / SPLIT;
    const int chunk = blockIdx.x % SPLIT;
    const int tid   = threadIdx.x;
    const int warp  = tid >> 5;
    const int lane  = tid & 31;
    const float bias = __ldg(bptr);

    // fixed per-thread weight slice (registers)
    const float4 w4 = reinterpret_cast<const float4*>(w)[tid];

    float4 acc = make_float4(0.f, 0.f, 0.f, 0.f);
    float lsum = 0.f;                               // only tid%8==0 uses it

    const int s0 = chunk * CHUNK;
    const float4* xbase = reinterpret_cast<const float4*>(
        x + (size_t)b * S_ * H_) + tid;             // + s*(H_/4) per row

    #pragma unroll 1
    for (int tile = 0; tile < CHUNK / TILE; tile++) {
        const int sb = s0 + tile * TILE;

        // Phase A: load 8 rows (front-batched -> MLP=8), partial dots
        float4 xr[TILE];
        #pragma unroll
        for (int s = 0; s < TILE; s++)
            xr[s] = xbase[(size_t)(sb + s) * (H_ / 4)];

        float d[TILE];
        #pragma unroll
        for (int s = 0; s < TILE; s++)
            d[s] = xr[s].x * w4.x + xr[s].y * w4.y
                 + xr[s].z * w4.z + xr[s].w * w4.w;

        // warp reduce each dot
        #pragma unroll
        for (int s = 0; s < TILE; s++) {
            #pragma unroll
            for (int off = 16; off; off >>= 1)
                d[s] += __shfl_xor_sync(0xffffffffu, d[s], off);
        }
        if (lane == 0) {
            #pragma unroll
            for (int s = 0; s < TILE; s++)
                red[warp * TILE + s] = d[s];
        }
        __syncthreads();

        // cross-warp reduce: 64 threads, groups of 8 lanes per timestep
        if (tid < 64) {
            const int s = tid >> 3;        // timestep within tile
            const int j = tid & 7;         // warp index
            float v = red[j * TILE + s];
            v += __shfl_xor_sync(0xffffffffu, v, 4);
            v += __shfl_xor_sync(0xffffffffu, v, 2);
            v += __shfl_xor_sync(0xffffffffu, v, 1);
            if (j == 0) {
                const float t = __expf(tanhf(v + bias));
                tt[s] = t;
                g_expE[(size_t)b * S_ + sb + s] = t;
                lsum += t;
            }
        }
        __syncthreads();

        // Phase B: consume xr[] from registers
        #pragma unroll
        for (int s = 0; s < TILE; s++) {
            const float t = tt[s];
            acc.x += t * xr[s].x;
            acc.y += t * xr[s].y;
            acc.z += t * xr[s].z;
            acc.w += t * xr[s].w;
        }
        __syncthreads();   // protect tt/red for next tile
    }

    // write partial context (each thread owns its own float4 slot)
    reinterpret_cast<float4*>(
        g_partC + ((size_t)b * SPLIT + chunk) * H_)[tid] = acc;

    // combine the 8 lsum owners (tid = 0,8,...,56)
    if (tid < 64 && (tid & 7) == 0) lred[tid >> 3] = lsum;
    __syncthreads();
    if (tid == 0) {
        float l = 0.f;
        #pragma unroll
        for (int i = 0; i < TILE; i++) l += lred[i];
        g_partL[b * SPLIT + chunk] = l;
    }
}

// ---------------------------------------------------------------------------
// Pass 2: per-batch combine of SPLIT partials -> context [B,H] and 1/l.
// ---------------------------------------------------------------------------
__global__ __launch_bounds__(THREADS)
void pass2_kernel(float* __restrict__ ctx_out)
{
    const int b   = blockIdx.x;
    const int tid = threadIdx.x;
    __shared__ float s_inv;

    if (tid < 32) {
        float l = 0.f;
        for (int c = tid; c < SPLIT; c += 32)
            l += g_partL[b * SPLIT + c];
        #pragma unroll
        for (int off = 16; off; off >>= 1)
            l += __shfl_xor_sync(0xffffffffu, l, off);
        if (tid == 0) {
            float inv = 1.f / l;
            s_inv = inv;
            g_linv[b] = inv;
        }
    }
    __syncthreads();
    const float inv = s_inv;

    float4 acc = make_float4(0.f, 0.f, 0.f, 0.f);
    #pragma unroll
    for (int c = 0; c < SPLIT; c++) {
        float4 v = reinterpret_cast<const float4*>(
            g_partC + ((size_t)b * SPLIT + c) * H_)[tid];
        acc.x += v.x; acc.y += v.y; acc.z += v.z; acc.w += v.w;
    }
    acc.x *= inv; acc.y *= inv; acc.z *= inv; acc.w *= inv;
    reinterpret_cast<float4*>(ctx_out + (size_t)b * H_)[tid] = acc;
}

// ---------------------------------------------------------------------------
// Pass 3: weights[b,s] = expE[b,s] / l[b]   (float4: S_ % 4 == 0)
// ---------------------------------------------------------------------------
__global__ __launch_bounds__(THREADS)
void pass3_kernel(float* __restrict__ w_out)
{
    const int i = blockIdx.x * THREADS + threadIdx.x;  // over B_*S_/4
    if (i < B_ * S_ / 4) {
        const int b = i / (S_ / 4);
        const float inv = g_linv[b];
        float4 e = reinterpret_cast<const float4*>(g_expE)[i];
        e.x *= inv; e.y *= inv; e.z *= inv; e.w *= inv;
        reinterpret_cast<float4*>(w_out)[i] = e;
    }
}

extern "C" void kernel_launch(void* const* d_in, const int* in_sizes, int n_in,
                              void* d_out, int out_size)
{
    const float* x    = (const float*)d_in[0];   // rnn_output [B,S,H]
    const float* w    = (const float*)d_in[1];   // attn_w [H]
    const float* bptr = (const float*)d_in[2];   // attn_b scalar

    float* out = (float*)d_out;                  // context [B,H] then weights [B,S]
    float* ctx_out = out;
    float* wts_out = out + (size_t)B_ * H_;

    pass1_kernel<<<B_ * SPLIT, THREADS>>>(x, w, bptr);
    pass2_kernel<<<B_, THREADS>>>(ctx_out);
    pass3_kernel<<<(B_ * S_ / 4 + THREADS - 1) / THREADS, THREADS>>>(wts_out);
}